// round 5
// baseline (speedup 1.0000x reference)
#include <cuda_runtime.h>

// ChunkedValueCrossAttn: softmax over a single context token == 1.0, so
// y[b,c,h,w] = (Wo @ (Wv @ context[b]))[c] + bo[c] — a constant per (b,c)
// broadcast over HxW. x/Wq/Wk are dead inputs.
//
// Shapes: B=2, C=64, H=W=1024, inner=32, ctx=16.
// out: [2, 64, 1024, 1024] f32 = 536.9 MB write-only -> HBM store-bound.
//
// Fused, barrier-free: every warp redundantly computes its block's constant
// (16 FMAs/lane + xor-butterfly -> sum in ALL lanes; no shared, no sync),
// then streams 8 plain float4 stores per thread. __stcs regressed hard in
// round 4 (DRAM 79.6%->57.9%) — plain STG.128 is the fast path here.
// Block range = 32KB, wholly inside one 4MB (b,c) slab: slab = blockIdx>>7.

#define B_       2
#define CQ_      64
#define INNER_   32
#define CTX_     16
#define TPB_     256
#define F4_PER_THREAD_ 8
#define F4_PER_BLOCK_  (TPB_ * F4_PER_THREAD_)   // 2048 float4 = 32KB

__global__ void __launch_bounds__(TPB_) fused_fill_kernel(
        float4* __restrict__ out,
        const float* __restrict__ context,
        const float* __restrict__ Wv,
        const float* __restrict__ Wo,
        const float* __restrict__ bo) {
    unsigned int slab = blockIdx.x >> 7;       // 128 blocks per slab
    unsigned int b = slab >> 6;                // batch index
    unsigned int c = slab & 63u;               // channel index

    // Every warp computes the constant redundantly — no cross-warp sync.
    int o = threadIdx.x & 31;                  // inner index, one per lane
    float v = 0.f;
    #pragma unroll
    for (int j = 0; j < CTX_; ++j)
        v += Wv[o * CTX_ + j] * context[b * CTX_ + j];
    float p = Wo[c * INNER_ + o] * v;
    #pragma unroll
    for (int off = 16; off > 0; off >>= 1)
        p += __shfl_xor_sync(0xFFFFFFFFu, p, off);   // all lanes hold the sum
    float val = p + bo[c];

    float4 f = make_float4(val, val, val, val);
    unsigned int base = blockIdx.x * (unsigned)F4_PER_BLOCK_ + threadIdx.x;
    #pragma unroll
    for (int k = 0; k < F4_PER_THREAD_; ++k)
        out[base + k * (unsigned)TPB_] = f;
}

extern "C" void kernel_launch(void* const* d_in, const int* in_sizes, int n_in,
                              void* d_out, int out_size) {
    // metadata order: x, context, Wq, Wk, Wv, Wo, bo
    const float* context = (const float*)d_in[1];
    const float* Wv      = (const float*)d_in[4];
    const float* Wo      = (const float*)d_in[5];
    const float* bo      = (const float*)d_in[6];

    // out_size = 134,217,728 floats = 33,554,432 float4 -> 16384 blocks exact
    int n4 = out_size / 4;
    int blocks = n4 / F4_PER_BLOCK_;
    fused_fill_kernel<<<blocks, TPB_>>>((float4*)d_out, context, Wv, Wo, bo);
}

// round 6
// speedup vs baseline: 1.7630x; 1.7630x over previous
#include <cuda_runtime.h>

// ChunkedValueCrossAttn: softmax over a single context token == 1.0, so
// y[b,c,h,w] = (Wo @ (Wv @ context[b]))[c] + bo[c] — a constant per (b,c)
// broadcast over HxW. x/Wq/Wk are dead inputs.
//
// Shapes: B=2, C=64, H=W=1024, inner=32, ctx=16.
// out: [2, 64, 1024, 1024] f32 = 536.9 MB write-only -> HBM store-bound.
//
// Single-wave fused kernel: 1024 blocks (8 per 4MB slab), each block owns a
// contiguous 512KB range in exactly ONE (b,c) slab. Warp 0 computes the
// constant (prologue load traffic 16x lower than round 3, amortized over
// 128 f4 stores per thread), one __syncthreads, then a pure STG.128 stream.
// Lesson from rounds 4-5: per-warp redundant prologue loads flood L1tex
// (scattered Wv LDGs -> 8x the store wavefronts) — never again.

#define B_       2
#define CQ_      64
#define INNER_   32
#define CTX_     16
#define TPB_     256
#define F4_PER_THREAD_ 128
#define F4_PER_BLOCK_  (TPB_ * F4_PER_THREAD_)   // 32768 float4 = 512KB
#define BLOCKS_PER_SLAB_ 8                        // 2^18 f4 / 32768

__global__ void __launch_bounds__(TPB_) fused_fill_kernel(
        float4* __restrict__ out,
        const float* __restrict__ context,
        const float* __restrict__ Wv,
        const float* __restrict__ Wo,
        const float* __restrict__ bo) {
    __shared__ float s_c;

    unsigned int slab = blockIdx.x >> 3;       // 8 blocks per slab
    unsigned int b = slab >> 6;                // batch index
    unsigned int c = slab & 63u;               // channel index

    if (threadIdx.x < 32) {
        int o = threadIdx.x;                   // inner index, one per lane
        float v = 0.f;
        #pragma unroll
        for (int j = 0; j < CTX_; ++j)
            v += Wv[o * CTX_ + j] * context[b * CTX_ + j];
        float p = Wo[c * INNER_ + o] * v;
        #pragma unroll
        for (int off = 16; off > 0; off >>= 1)
            p += __shfl_xor_sync(0xFFFFFFFFu, p, off);
        if (o == 0) s_c = p + bo[c];
    }
    __syncthreads();

    float val = s_c;
    float4 f = make_float4(val, val, val, val);
    float4* p = out + (size_t)blockIdx.x * F4_PER_BLOCK_ + threadIdx.x;
    #pragma unroll 16
    for (int k = 0; k < F4_PER_THREAD_; ++k)
        p[k * TPB_] = f;
}

extern "C" void kernel_launch(void* const* d_in, const int* in_sizes, int n_in,
                              void* d_out, int out_size) {
    // metadata order: x, context, Wq, Wk, Wv, Wo, bo
    const float* context = (const float*)d_in[1];
    const float* Wv      = (const float*)d_in[4];
    const float* Wo      = (const float*)d_in[5];
    const float* bo      = (const float*)d_in[6];

    // out_size = 134,217,728 floats = 33,554,432 float4 -> 1024 blocks exact
    int n4 = out_size / 4;
    int blocks = n4 / F4_PER_BLOCK_;   // 1024
    fused_fill_kernel<<<blocks, TPB_>>>((float4*)d_out, context, Wv, Wo, bo);
}

// round 7
// speedup vs baseline: 1.9323x; 1.0961x over previous
#include <cuda_runtime.h>

// ChunkedValueCrossAttn: softmax over a single context token == 1.0, so
// y[b,c,h,w] = (Wo @ (Wv @ context[b]))[c] + bo[c] — a constant per (b,c)
// broadcast over HxW. x/Wq/Wk are dead inputs.
//
// Shapes: B=2, C=64, H=W=1024, inner=32, ctx=16.
// out: [2, 64, 1024, 1024] f32 = 536.9 MB write-only -> HBM store-bound.
//
// Fused, 4096 blocks x 32 float4/thread (128KB per block, inside one slab).
// Evidence so far: store engine wants many surplus blocks (16384 blks:
// DRAM 81%; 1024 blks: DRAM 69%); prologue cost scales with block count
// (round 3's 16384 prologues cost ~1.4us). 4096 is the midpoint: 28
// blocks/SM of backfill, prologue count cut 4x. Warp-0-only constant
// compute (redundant per-warp compute flooded L1tex in rounds 4-5).

#define B_       2
#define CQ_      64
#define INNER_   32
#define CTX_     16
#define TPB_     256
#define F4_PER_THREAD_ 32
#define F4_PER_BLOCK_  (TPB_ * F4_PER_THREAD_)   // 8192 float4 = 128KB
// 2^18 f4 per slab / 8192 = 32 blocks per slab

__global__ void __launch_bounds__(TPB_) fused_fill_kernel(
        float4* __restrict__ out,
        const float* __restrict__ context,
        const float* __restrict__ Wv,
        const float* __restrict__ Wo,
        const float* __restrict__ bo) {
    __shared__ float s_c;

    unsigned int slab = blockIdx.x >> 5;       // 32 blocks per slab
    unsigned int b = slab >> 6;                // batch index
    unsigned int c = slab & 63u;               // channel index

    if (threadIdx.x < 32) {
        int o = threadIdx.x;                   // inner index, one per lane
        float v = 0.f;
        #pragma unroll
        for (int j = 0; j < CTX_; ++j)
            v += Wv[o * CTX_ + j] * context[b * CTX_ + j];
        float p = Wo[c * INNER_ + o] * v;
        #pragma unroll
        for (int off = 16; off > 0; off >>= 1)
            p += __shfl_xor_sync(0xFFFFFFFFu, p, off);
        if (o == 0) s_c = p + bo[c];
    }
    __syncthreads();

    float val = s_c;
    float4 f = make_float4(val, val, val, val);
    float4* p = out + (size_t)blockIdx.x * F4_PER_BLOCK_ + threadIdx.x;
    #pragma unroll 8
    for (int k = 0; k < F4_PER_THREAD_; ++k)
        p[k * TPB_] = f;
}

extern "C" void kernel_launch(void* const* d_in, const int* in_sizes, int n_in,
                              void* d_out, int out_size) {
    // metadata order: x, context, Wq, Wk, Wv, Wo, bo
    const float* context = (const float*)d_in[1];
    const float* Wv      = (const float*)d_in[4];
    const float* Wo      = (const float*)d_in[5];
    const float* bo      = (const float*)d_in[6];

    // out_size = 134,217,728 floats = 33,554,432 float4 -> 4096 blocks exact
    int n4 = out_size / 4;
    int blocks = n4 / F4_PER_BLOCK_;   // 4096
    fused_fill_kernel<<<blocks, TPB_>>>((float4*)d_out, context, Wv, Wo, bo);
}

// round 8
// speedup vs baseline: 2.0333x; 1.0522x over previous
#include <cuda_runtime.h>

// ChunkedValueCrossAttn: softmax over a single context token == 1.0, so
// y[b,c,h,w] = (Wo @ (Wv @ context[b]))[c] + bo[c] — a constant per (b,c)
// broadcast over HxW. x/Wq/Wk are dead inputs.
//
// Shapes: B=2, C=64, H=W=1024, inner=32, ctx=16.
// out: [2, 64, 1024, 1024] f32 = 536.9 MB write-only -> HBM store-bound.
//
// Settled by rounds 1-7: store engine wants 16384 blocks x 8 f4/thread
// (DRAM 81.1%, the best measured). This round fixes the fused prologue's
// L1tex pollution: warp 0 loads Wv via 4 coalesced LDG.128 into padded
// shared (was: 16 strided scalar loads/lane = ~260 wavefronts/block),
// then computes the constant from conflict-free LDS. ~25x less prologue
// global traffic at identical math.

#define B_       2
#define CQ_      64
#define INNER_   32
#define CTX_     16
#define TPB_     256
#define F4_PER_THREAD_ 8
#define F4_PER_BLOCK_  (TPB_ * F4_PER_THREAD_)   // 2048 float4 = 32KB

__global__ void __launch_bounds__(TPB_) fused_fill_kernel(
        float4* __restrict__ out,
        const float* __restrict__ context,
        const float* __restrict__ Wv,
        const float* __restrict__ Wo,
        const float* __restrict__ bo) {
    __shared__ float s_wv[INNER_][CTX_ + 1];   // 17-float rows: LDS conflict-free
    __shared__ float s_ctx[CTX_];
    __shared__ float s_c;

    unsigned int slab = blockIdx.x >> 7;       // 128 blocks per slab
    unsigned int b = slab >> 6;                // batch index
    unsigned int c = slab & 63u;               // channel index

    if (threadIdx.x < 32) {
        int l = threadIdx.x;

        // Coalesced Wv load: 128 float4 total -> 4 LDG.128 per lane.
        const float4* Wv4 = (const float4*)Wv;
        #pragma unroll
        for (int t = 0; t < 4; ++t) {
            int idx = t * 32 + l;              // float4 index 0..127
            float4 w = Wv4[idx];
            float* dst = &s_wv[idx >> 2][(idx & 3) * 4];
            dst[0] = w.x; dst[1] = w.y; dst[2] = w.z; dst[3] = w.w;
        }
        if (l < CTX_) s_ctx[l] = context[b * CTX_ + l];
        float wo = Wo[c * INNER_ + l];         // coalesced 128B, 1 wavefront
        __syncwarp();

        // v_l = dot(Wv[l,:], ctx);  LDS banks: 17l+j -> conflict-free per j.
        float v = 0.f;
        #pragma unroll
        for (int j = 0; j < CTX_; ++j)
            v += s_wv[l][j] * s_ctx[j];

        float p = wo * v;
        #pragma unroll
        for (int off = 16; off > 0; off >>= 1)
            p += __shfl_xor_sync(0xFFFFFFFFu, p, off);
        if (l == 0) s_c = p + bo[c];
    }
    __syncthreads();

    float val = s_c;
    float4 f = make_float4(val, val, val, val);
    unsigned int base = blockIdx.x * (unsigned)F4_PER_BLOCK_ + threadIdx.x;
    #pragma unroll
    for (int k = 0; k < F4_PER_THREAD_; ++k)
        out[base + k * (unsigned)TPB_] = f;
}

extern "C" void kernel_launch(void* const* d_in, const int* in_sizes, int n_in,
                              void* d_out, int out_size) {
    // metadata order: x, context, Wq, Wk, Wv, Wo, bo
    const float* context = (const float*)d_in[1];
    const float* Wv      = (const float*)d_in[4];
    const float* Wo      = (const float*)d_in[5];
    const float* bo      = (const float*)d_in[6];

    // out_size = 134,217,728 floats = 33,554,432 float4 -> 16384 blocks exact
    int n4 = out_size / 4;
    int blocks = n4 / F4_PER_BLOCK_;   // 16384
    fused_fill_kernel<<<blocks, TPB_>>>((float4*)d_out, context, Wv, Wo, bo);
}